// round 4
// baseline (speedup 1.0000x reference)
#include <cuda_runtime.h>

// Problem constants (fixed shapes per reference):
//   white/black: [4096, 32] int32 (JAX default x64-disabled downcasts int64)
//   stm: [4096] int32
//   emb_table:   [40960, 2048] f32
//   W1: [128, 4096] f32, b1: [128] f32, W2: [1, 128] f32, b2: [1] f32
//   out: [4096, 1] f32
#define BATCH 4096
#define LFEAT 32
#define DIM   2048
#define KTOT  (2 * DIM)     // 4096
#define NFEAT 40960
#define NSPLIT 8            // K-splits for the layer-1 GEMM

// Scratch (static __device__ arrays; no allocation APIs anywhere).
__device__ float g_X[(size_t)BATCH * KTOT];                 // 64 MB: stm-ordered concat inputs
__device__ float g_Hs[(size_t)NSPLIT * BATCH * 128];        // 16 MB: per-K-split partial H

// ---------------------------------------------------------------------------
// K1: masked embedding gather-sum + stm-conditioned concat into g_X.
// One block per batch row; 512 threads, one float4 of the 2048-dim each.
// ---------------------------------------------------------------------------
__global__ void __launch_bounds__(512) gather_kernel(
    const int* __restrict__ white,
    const int* __restrict__ black,
    const int* __restrict__ stm,
    const float* __restrict__ emb)
{
    int r = blockIdx.x;
    int t = threadIdx.x;  // 0..511 -> float4 lane over D=2048

    __shared__ int sidx[2 * LFEAT];
    if (t < 2 * LFEAT) {
        sidx[t] = (t < LFEAT) ? white[r * LFEAT + t]
                              : black[r * LFEAT + (t - LFEAT)];
    }
    __syncthreads();

    float4 accW = make_float4(0.f, 0.f, 0.f, 0.f);
    float4 accB = make_float4(0.f, 0.f, 0.f, 0.f);

    #pragma unroll 4
    for (int l = 0; l < LFEAT; l++) {
        int iw = sidx[l];
        // index 0 = padding (masked); bound check is defensive (no-crash on
        // dtype surprises -> rel_err signal instead of IMA)
        if (iw != 0 && (unsigned)iw < NFEAT) {
            float4 v = __ldg(((const float4*)(emb + (size_t)iw * DIM)) + t);
            accW.x += v.x; accW.y += v.y; accW.z += v.z; accW.w += v.w;
        }
        int ib = sidx[LFEAT + l];
        if (ib != 0 && (unsigned)ib < NFEAT) {
            float4 v = __ldg(((const float4*)(emb + (size_t)ib * DIM)) + t);
            accB.x += v.x; accB.y += v.y; accB.z += v.z; accB.w += v.w;
        }
    }

    float4* row = (float4*)(g_X + (size_t)r * KTOT);
    const int HALF4 = DIM / 4;  // 512 float4 per half
    if (stm[r] == 1) { row[t] = accW; row[HALF4 + t] = accB; }
    else             { row[t] = accB; row[HALF4 + t] = accW; }
}

// ---------------------------------------------------------------------------
// K2: split-K fp32 GEMM: H += X[128-row tile] @ W1^T (all 128 cols).
// grid = (BATCH/128, NSPLIT). Block tile 128x128, BK=8, 256 threads, 8x8
// microtiles. Each (m,s) block writes its raw partial sums to g_Hs[s] slice
// (deterministic: no atomics).
// ---------------------------------------------------------------------------
__global__ void __launch_bounds__(256) mlp1_kernel(const float* __restrict__ W1)
{
    __shared__ float As[8][132];  // padded to avoid store bank conflicts
    __shared__ float Bs[8][132];

    const int tid = threadIdx.x;
    const int tx = tid & 15;       // 0..15 -> col group
    const int ty = tid >> 4;       // 0..15 -> row group
    const int rowBase = blockIdx.x * 128;
    const int ksplit  = blockIdx.y;
    const int k0base  = ksplit * (KTOT / NSPLIT);   // 512-wide K range
    const int kEnd    = k0base + (KTOT / NSPLIT);

    const int ldRow = tid >> 1;        // 0..127
    const int ldK   = (tid & 1) * 4;   // 0 or 4

    const float* Xp = g_X + (size_t)(rowBase + ldRow) * KTOT + ldK;
    const float* Wp = W1  + (size_t)ldRow * KTOT + ldK;

    float acc[8][8];
    #pragma unroll
    for (int i = 0; i < 8; i++)
        #pragma unroll
        for (int j = 0; j < 8; j++) acc[i][j] = 0.f;

    for (int k0 = k0base; k0 < kEnd; k0 += 8) {
        float4 av = *(const float4*)(Xp + k0);
        float4 bv = *(const float4*)(Wp + k0);
        __syncthreads();
        As[ldK + 0][ldRow] = av.x; As[ldK + 1][ldRow] = av.y;
        As[ldK + 2][ldRow] = av.z; As[ldK + 3][ldRow] = av.w;
        Bs[ldK + 0][ldRow] = bv.x; Bs[ldK + 1][ldRow] = bv.y;
        Bs[ldK + 2][ldRow] = bv.z; Bs[ldK + 3][ldRow] = bv.w;
        __syncthreads();

        #pragma unroll
        for (int kk = 0; kk < 8; kk++) {
            float a[8], b[8];
            #pragma unroll
            for (int i = 0; i < 8; i++) a[i] = As[kk][ty * 8 + i];
            #pragma unroll
            for (int j = 0; j < 8; j++) b[j] = Bs[kk][tx * 8 + j];
            #pragma unroll
            for (int i = 0; i < 8; i++)
                #pragma unroll
                for (int j = 0; j < 8; j++)
                    acc[i][j] = fmaf(a[i], b[j], acc[i][j]);
        }
    }

    float* Hslice = g_Hs + (size_t)ksplit * BATCH * 128;
    #pragma unroll
    for (int i = 0; i < 8; i++) {
        int row = rowBase + ty * 8 + i;
        float* hr = Hslice + (size_t)row * 128 + tx * 8;
        #pragma unroll
        for (int j = 0; j < 8; j++) hr[j] = acc[i][j];
    }
}

// ---------------------------------------------------------------------------
// K3: sum K-split partials, bias+ReLU, dot with W2, add b2. One warp per row.
// ---------------------------------------------------------------------------
__global__ void __launch_bounds__(256) mlp2_kernel(
    const float* __restrict__ b1, const float* __restrict__ W2,
    const float* __restrict__ b2, float* __restrict__ out)
{
    int warp = threadIdx.x >> 5;
    int lane = threadIdx.x & 31;
    int r = blockIdx.x * 8 + warp;

    float p = 0.f;
    #pragma unroll
    for (int jj = 0; jj < 4; jj++) {
        int j = lane + jj * 32;
        float h = 0.f;
        #pragma unroll
        for (int s = 0; s < NSPLIT; s++)
            h += g_Hs[((size_t)s * BATCH + r) * 128 + j];
        h += __ldg(b1 + j);
        h = fmaxf(h, 0.f);
        p += h * __ldg(W2 + j);
    }
    #pragma unroll
    for (int o = 16; o > 0; o >>= 1) p += __shfl_xor_sync(0xffffffffu, p, o);
    if (lane == 0) out[r] = p + b2[0];
}

// ---------------------------------------------------------------------------
extern "C" void kernel_launch(void* const* d_in, const int* in_sizes, int n_in,
                              void* d_out, int out_size)
{
    const int* white = (const int*)d_in[0];
    const int* black = (const int*)d_in[1];
    const int* stm   = (const int*)d_in[2];
    const float* emb = (const float*)d_in[3];
    const float* W1  = (const float*)d_in[4];
    const float* b1  = (const float*)d_in[5];
    const float* W2  = (const float*)d_in[6];
    const float* b2  = (const float*)d_in[7];
    float* out = (float*)d_out;

    gather_kernel<<<BATCH, 512>>>(white, black, stm, emb);
    mlp1_kernel<<<dim3(BATCH / 128, NSPLIT), 256>>>(W1);
    mlp2_kernel<<<BATCH / 8, 256>>>(b1, W2, b2, out);
}